// round 5
// baseline (speedup 1.0000x reference)
#include <cuda_runtime.h>
#include <math.h>

#define Nn 1024
#define Cc 8192
#define Dd 16
#define ODim 128
#define EPSF 1e-15f
#define CLIPMAXF 10000.0f
#define NB 16                       // 1024/64 tiles per side
#define NTRI (NB*(NB+1)/2)          // 136 triangular 64x64 tiles
#define NOMEGA (NTRI*2)             // 272 half-tiles (64x32)
#define NREAL 512                   // real-dist blocks (4 i-rows, 512 j each)
#define NTOT (NOMEGA + NREAL)       // 784

// ---------- state (device globals; zero at load, re-zeroed by finalize) ----------
__device__ float    g_colR[Nn];
__device__ float    g_colA[Nn];
__device__ double   g_sumsqR;
__device__ double   g_sumsqA;
__device__ double   g_overlap;
__device__ double   g_exceed;
__device__ double   g_shape;
__device__ double   g_positive;
__device__ unsigned g_done;

__global__ void __launch_bounds__(256, 6)
k_all(const int* __restrict__ idI, const int* __restrict__ par,
      const float* __restrict__ omega, const float* __restrict__ child,
      const float* __restrict__ resv, const float* __restrict__ leaves,
      const float* __restrict__ layerDist, float* __restrict__ out) {
    __shared__ float sA[32][64];
    __shared__ float sB[32][32];
    __shared__ float sInnA[64], sInnB[32];
    __shared__ float scol[32], srow[64];
    __shared__ __align__(16) float sI[4][48];
    __shared__ bool isLast;

    int tid = threadIdx.x;
    int w = tid >> 5, lane = tid & 31;
    int b = blockIdx.x;

    if (b < NOMEGA) {
        // ============ omega half-tile: 64 rows (bi) x 32 cols (bj,h) ============
        int t2 = b >> 1, h = b & 1;
        int bi = 0;
        while (t2 >= NB - bi) { t2 -= NB - bi; bi++; }
        int bj = bi + t2;
        bool diag = (bi == bj);
        int jbase = bj * 64 + h * 32;

        if (tid < 64) { srow[tid] = 0.f; if (tid < 32) scol[tid] = 0.f; }

        float c[4][2];
#pragma unroll
        for (int m = 0; m < 4; m++) { c[m][0] = 0.f; c[m][1] = 0.f; }

        int ty = tid >> 4, tx = tid & 15;
        int iloc = ty * 4, jloc = tx * 2;

        for (int kc = 0; kc < ODim; kc += 32) {
            __syncthreads();
#pragma unroll
            for (int s = 0; s < 2; s++) {
                int f = tid + s * 256;
                int r = f & 63, q = f >> 6;
                float4 va = ((const float4*)omega)[(size_t)(bi * 64 + r) * (ODim / 4) + (kc >> 2) + q];
                sA[q * 4 + 0][r] = va.x; sA[q * 4 + 1][r] = va.y;
                sA[q * 4 + 2][r] = va.z; sA[q * 4 + 3][r] = va.w;
            }
            {
                int r = tid & 31, q = tid >> 5;
                float4 vb = ((const float4*)omega)[(size_t)(jbase + r) * (ODim / 4) + (kc >> 2) + q];
                sB[q * 4 + 0][r] = vb.x; sB[q * 4 + 1][r] = vb.y;
                sB[q * 4 + 2][r] = vb.z; sB[q * 4 + 3][r] = vb.w;
            }
            __syncthreads();
#pragma unroll
            for (int k = 0; k < 32; k++) {
                float4 av = *(const float4*)&sA[k][iloc];
                float2 bv = *(const float2*)&sB[k][jloc];
                c[0][0] += av.x * bv.x; c[0][1] += av.x * bv.y;
                c[1][0] += av.y * bv.x; c[1][1] += av.y * bv.y;
                c[2][0] += av.z * bv.x; c[2][1] += av.z * bv.y;
                c[3][0] += av.w * bv.x; c[3][1] += av.w * bv.y;
            }
        }

        // inner norms for this tile's rows/cols (L2-hot)
        if (tid < 96) {
            int r = (tid < 64) ? tid : (tid - 64);
            int row = (tid < 64) ? (bi * 64 + r) : (jbase + r);
            const float4* p = (const float4*)(omega + (size_t)row * ODim);
            float s = 0.f;
#pragma unroll
            for (int q = 0; q < ODim / 4; q++) {
                float4 v = p[q];
                s += v.x * v.x + v.y * v.y + v.z * v.z + v.w * v.w;
            }
            if (tid < 64) sInnA[r] = s; else sInnB[r] = s;
        }
        __syncthreads();

        float innI[4], innJ[2];
#pragma unroll
        for (int m = 0; m < 4; m++) innI[m] = sInnA[iloc + m];
        innJ[0] = sInnB[jloc]; innJ[1] = sInnB[jloc + 1];

        float colloc[2] = {0.f, 0.f};
        float rowloc[4] = {0.f, 0.f, 0.f, 0.f};
        float ssf = 0.f;
#pragma unroll
        for (int m = 0; m < 4; m++)
#pragma unroll
            for (int n = 0; n < 2; n++) {
                float a = fmaxf(innI[m] + innJ[n] - 2.0f * c[m][n], EPSF);
                ssf += a * a;
                colloc[n] += a;
                rowloc[m] += a;
            }
        if (!diag) ssf *= 2.0f;

        atomicAdd(&scol[jloc],     colloc[0]);
        atomicAdd(&scol[jloc + 1], colloc[1]);
        if (!diag) {
#pragma unroll
            for (int m = 0; m < 4; m++) atomicAdd(&srow[iloc + m], rowloc[m]);
        }

        double ss = (double)ssf;
#pragma unroll
        for (int off = 16; off > 0; off >>= 1)
            ss += __shfl_xor_sync(0xffffffffu, ss, off);
        if (lane == 0) atomicAdd(&g_sumsqA, ss);

        __syncthreads();
        if (tid < 32) atomicAdd(&g_colA[jbase + tid], scol[tid]);
        if (!diag && tid < 64) atomicAdd(&g_colA[bi * 64 + tid], srow[tid]);
    } else {
        // ============ realDist block: 4 i-rows x 512 j ============
        int rb = b - NOMEGA;
        int i0 = (rb >> 1) * 4;

        if (tid < 64) {
            int ii = tid >> 4, d = tid & 15;
            int idxi = __ldg(idI + i0 + ii);
            float cl = __ldg(child + (size_t)idxi * 32 + d);
            float ch = __ldg(child + (size_t)idxi * 32 + 16 + d);
            sI[ii][d]      = cl;
            sI[ii][16 + d] = ch;
            sI[ii][32 + d] = 1.0f / fmaxf(ch - cl, EPSF);
        }
        int idxi4[4];
#pragma unroll
        for (int ii = 0; ii < 4; ii++) idxi4[ii] = __ldg(idI + i0 + ii);
        __syncthreads();

        double ssq = 0.0, ovd = 0.0;
        double eAcc = 0.0, shAcc = 0.0, poAcc = 0.0;
        bool doPrep = (rb < 2);

#pragma unroll
        for (int q = 0; q < 2; q++) {
            int jglob = (rb & 1) * 512 + q * 256 + tid;
            int idxj = __ldg(idI + jglob);

            // prefetch gathers (MLP=4) before the compute body
            float acc[4];
#pragma unroll
            for (int ii = 0; ii < 4; ii++)
                acc[ii] = __ldg(layerDist + (size_t)idxi4[ii] * Cc + idxj);

            const float4* pl = (const float4*)(child + (size_t)idxj * 32);
            const float4* ph = (const float4*)(child + (size_t)idxj * 32 + 16);

            float cd[4] = {0.f, 0.f, 0.f, 0.f};
            float ov[4] = {0.f, 0.f, 0.f, 0.f};
#pragma unroll
            for (int u = 0; u < 4; u++) {
                float4 l = pl[u], hh = ph[u];
#pragma unroll
                for (int ii = 0; ii < 4; ii++) {
                    float4 a = *(const float4*)&sI[ii][u * 4];
                    float4 bb = *(const float4*)&sI[ii][16 + u * 4];
                    float4 v = *(const float4*)&sI[ii][32 + u * 4];
                    cd[ii] += fabsf(a.x - l.x) + fabsf(a.y - l.y)
                            + fabsf(a.z - l.z) + fabsf(a.w - l.w);
                    ov[ii] += fmaxf(fminf(bb.x, hh.x) - fmaxf(a.x, l.x), 0.f) * v.x
                            + fmaxf(fminf(bb.y, hh.y) - fmaxf(a.y, l.y), 0.f) * v.y
                            + fmaxf(fminf(bb.z, hh.z) - fmaxf(a.z, l.z), 0.f) * v.z
                            + fmaxf(fminf(bb.w, hh.w) - fmaxf(a.w, l.w), 0.f) * v.w;
                }
            }

            float colsum = 0.f, ssqf = 0.f, ovf = 0.f;
#pragma unroll
            for (int ii = 0; ii < 4; ii++) {
                float r = acc[ii] + cd[ii];
                colsum += r;
                ssqf += r * r;
                if (i0 + ii != jglob) ovf += ov[ii];
            }
            atomicAdd(&g_colR[jglob], colsum);
            ssq += (double)ssqf;
            ovd += (double)ovf;

            // ---- fused per-node prep (blocks rb=0,1 cover all nodes) ----
            if (doPrep) {
                int p = __ldg(par + jglob);
                float leaf = __ldg(leaves + idxj);
                const float HPI = (float)(3.14159265358979323846 * 0.5);
                const float CAP = (float)(3.14159265358979323846 * 0.49999);
                const float4* prl = (const float4*)(resv + (size_t)p * 32);
                const float4* prh = (const float4*)(resv + (size_t)p * 32 + 16);
                float exceed = 0.f, shape = 0.f, pos = 0.f;
#pragma unroll
                for (int u = 0; u < 4; u++) {
                    float4 cl = pl[u], ch = ph[u];
                    float4 rl = prl[u], rh = prh[u];
                    float cc[4] = {cl.x, cl.y, cl.z, cl.w};
                    float ee[4] = {ch.x, ch.y, ch.z, ch.w};
                    float aa[4] = {rl.x, rl.y, rl.z, rl.w};
                    float zz[4] = {rh.x, rh.y, rh.z, rh.w};
#pragma unroll
                    for (int d = 0; d < 4; d++) {
                        float diff = ee[d] - cc[d];
                        exceed += fmaxf((aa[d] + 1.0f) - cc[d], 0.f)
                                + fmaxf(ee[d] - (zz[d] + 1.0f), 0.f);
                        float numer = fmaxf(diff / (zz[d] - aa[d]), EPSF);
                        float sdiv  = fminf(numer / leaf, CAP);
                        shape += fminf(fabsf(tanf((sdiv - 1.0f) * HPI)), CLIPMAXF);
                        pos += fmaxf(expf(-diff), EPSF);
                    }
                }
                eAcc += (double)exceed; shAcc += (double)shape; poAcc += (double)pos;
            }
        }

#pragma unroll
        for (int off = 16; off > 0; off >>= 1) {
            ssq += __shfl_xor_sync(0xffffffffu, ssq, off);
            ovd += __shfl_xor_sync(0xffffffffu, ovd, off);
        }
        if (lane == 0) {
            atomicAdd(&g_sumsqR, ssq);
            atomicAdd(&g_overlap, ovd);
        }
        if (doPrep) {
#pragma unroll
            for (int off = 16; off > 0; off >>= 1) {
                eAcc  += __shfl_xor_sync(0xffffffffu, eAcc,  off);
                shAcc += __shfl_xor_sync(0xffffffffu, shAcc, off);
                poAcc += __shfl_xor_sync(0xffffffffu, poAcc, off);
            }
            if (lane == 0) {
                atomicAdd(&g_exceed,   eAcc);
                atomicAdd(&g_shape,    shAcc);
                atomicAdd(&g_positive, poAcc);
            }
        }
    }

    // ================= last-block finalize + state re-zero =================
    __threadfence();
    if (tid == 0) isLast = (atomicAdd(&g_done, 1u) == NTOT - 1);
    __syncthreads();
    if (!isLast) return;
    __threadfence();

    double s1 = 0.0, s2 = 0.0;
#pragma unroll
    for (int q = 0; q < 4; q++) {
        int j = tid + q * 256;
        double r = (double)__ldcg(&g_colR[j]);
        double a = (double)__ldcg(&g_colA[j]);
        s1 += r * a;
        s2 += r * r;
        g_colR[j] = 0.f;
        g_colA[j] = 0.f;
    }
    __shared__ double r1[8], r2[8];
#pragma unroll
    for (int off = 16; off > 0; off >>= 1) {
        s1 += __shfl_xor_sync(0xffffffffu, s1, off);
        s2 += __shfl_xor_sync(0xffffffffu, s2, off);
    }
    if (lane == 0) { r1[w] = s1; r2[w] = s2; }
    __syncthreads();
    if (tid == 0) {
        double a = 0.0, cc2 = 0.0;
#pragma unroll
        for (int q = 0; q < 8; q++) { a += r1[q]; cc2 += r2[q]; }
        double sumsqR = __ldcg(&g_sumsqR);
        double sumsqA = __ldcg(&g_sumsqA);
        double nR = fmax(sqrt(sumsqR), 1e-15);
        double nA = fmax(sqrt(sumsqA), 1e-15);
        double val = sumsqA / (nA * nA) - 2.0 * (a / nR) / nA + (double)Nn * (cc2 / (nR * nR));
        double lossDist = sqrt(fmax(val, 0.0));
        out[0] = (float)(lossDist + __ldcg(&g_shape) + __ldcg(&g_exceed)
                         + __ldcg(&g_overlap) + __ldcg(&g_positive));
        g_sumsqR = 0.0; g_sumsqA = 0.0; g_overlap = 0.0;
        g_exceed = 0.0; g_shape = 0.0; g_positive = 0.0;
        g_done = 0u;
    }
}

// ---------------- launch ----------------
extern "C" void kernel_launch(void* const* d_in, const int* in_sizes, int n_in,
                              void* d_out, int out_size) {
    const int*   idI    = (const int*)d_in[0];
    const int*   par    = (const int*)d_in[1];
    const float* omega  = (const float*)d_in[2];
    const float* child  = (const float*)d_in[3];
    const float* resv   = (const float*)d_in[4];
    const float* leaves = (const float*)d_in[5];
    const float* layerD = (const float*)d_in[6];
    (void)in_sizes; (void)n_in; (void)out_size;

    k_all<<<NTOT, 256>>>(idI, par, omega, child, resv, leaves, layerD, (float*)d_out);
}

// round 6
// speedup vs baseline: 1.1157x; 1.1157x over previous
#include <cuda_runtime.h>
#include <math.h>

#define Nn 1024
#define Cc 8192
#define Dd 16
#define ODim 128
#define EPSF 1e-15f
#define CLIPMAXF 10000.0f
#define NB 16                      // 1024/64 tiles per side
#define NTRI (NB*(NB+1)/2)         // 136 triangular omega tiles
#define NREAL 256                  // real-dist blocks
#define NTOT (NTRI + NREAL)        // 392

// ---------- state (device globals; zero at load; finalize restores) ----------
// g_part slots: 0=sumsqR 1=overlap 2=exceed 3=shape 4=positive 5=sumsqA
__device__ double   g_part[NTOT][8];      // overwritten every run (no zeroing needed)
__device__ float    g_colRs[8][Nn];       // striped col sums (re-zeroed by finalize)
__device__ float    g_colAs[8][Nn];
__device__ unsigned g_done;

__global__ void __launch_bounds__(256, 4)
k_all(const int* __restrict__ idI, const int* __restrict__ par,
      const float* __restrict__ omega, const float* __restrict__ child,
      const float* __restrict__ resv, const float* __restrict__ leaves,
      const float* __restrict__ layerDist, float* __restrict__ out) {
    __shared__ float sA[32][64];
    __shared__ float sB[32][64];
    __shared__ float sInnA[64], sInnB[64];
    __shared__ float scol[64], srow[64];
    __shared__ __align__(16) float sI[8][48];
    __shared__ double sRed[8][6];
    __shared__ bool isLast;

    int tid = threadIdx.x;
    int w = tid >> 5, lane = tid & 31;
    int b = blockIdx.x;

    if (b < NTRI) {
        // ================= omega tile (64x64 triangular) =================
        int t = b, bi = 0;
        while (t >= NB - bi) { t -= NB - bi; bi++; }
        int bj = bi + t;
        bool diag = (bi == bj);

        if (tid < 64) { scol[tid] = 0.f; srow[tid] = 0.f; }

        float c[4][4];
#pragma unroll
        for (int m = 0; m < 4; m++)
#pragma unroll
            for (int n = 0; n < 4; n++) c[m][n] = 0.f;

        int ri = lane >> 3;
        int cj = lane & 7;
        int iloc = (w & 3) * 16 + ri * 4;
        int jloc = (w >> 2) * 32 + cj * 4;

        for (int kc = 0; kc < ODim; kc += 32) {
            __syncthreads();
#pragma unroll
            for (int s = 0; s < 2; s++) {
                int f = tid + s * 256;
                int r = f & 63, q = f >> 6;
                float4 va = ((const float4*)omega)[(size_t)(bi * 64 + r) * (ODim / 4) + (kc >> 2) + q];
                float4 vb = ((const float4*)omega)[(size_t)(bj * 64 + r) * (ODim / 4) + (kc >> 2) + q];
                sA[q * 4 + 0][r] = va.x; sA[q * 4 + 1][r] = va.y;
                sA[q * 4 + 2][r] = va.z; sA[q * 4 + 3][r] = va.w;
                sB[q * 4 + 0][r] = vb.x; sB[q * 4 + 1][r] = vb.y;
                sB[q * 4 + 2][r] = vb.z; sB[q * 4 + 3][r] = vb.w;
            }
            __syncthreads();
#pragma unroll
            for (int k = 0; k < 32; k++) {
                float4 av = *(const float4*)&sA[k][iloc];
                float4 bv = *(const float4*)&sB[k][jloc];
                c[0][0] += av.x * bv.x; c[0][1] += av.x * bv.y; c[0][2] += av.x * bv.z; c[0][3] += av.x * bv.w;
                c[1][0] += av.y * bv.x; c[1][1] += av.y * bv.y; c[1][2] += av.y * bv.z; c[1][3] += av.y * bv.w;
                c[2][0] += av.z * bv.x; c[2][1] += av.z * bv.y; c[2][2] += av.z * bv.z; c[2][3] += av.z * bv.w;
                c[3][0] += av.w * bv.x; c[3][1] += av.w * bv.y; c[3][2] += av.w * bv.z; c[3][3] += av.w * bv.w;
            }
        }

        // inner norms for this tile's rows/cols (L2-hot)
        if (tid < 128) {
            int r = tid & 63;
            int row = ((tid < 64) ? bi : bj) * 64 + r;
            const float4* p = (const float4*)(omega + (size_t)row * ODim);
            float s = 0.f;
#pragma unroll
            for (int q = 0; q < ODim / 4; q++) {
                float4 v = p[q];
                s += v.x * v.x + v.y * v.y + v.z * v.z + v.w * v.w;
            }
            if (tid < 64) sInnA[r] = s; else sInnB[r] = s;
        }
        __syncthreads();

        float innI[4], innJ[4];
#pragma unroll
        for (int m = 0; m < 4; m++) innI[m] = sInnA[iloc + m];
#pragma unroll
        for (int n = 0; n < 4; n++) innJ[n] = sInnB[jloc + n];

        float colloc[4] = {0.f, 0.f, 0.f, 0.f};
        float rowloc[4] = {0.f, 0.f, 0.f, 0.f};
        float ssf = 0.f;
#pragma unroll
        for (int m = 0; m < 4; m++)
#pragma unroll
            for (int n = 0; n < 4; n++) {
                float a = fmaxf(innI[m] + innJ[n] - 2.0f * c[m][n], EPSF);
                ssf += a * a;
                colloc[n] += a;
                rowloc[m] += a;
            }
        if (!diag) ssf *= 2.0f;

#pragma unroll
        for (int n = 0; n < 4; n++) atomicAdd(&scol[jloc + n], colloc[n]);
        if (!diag) {
#pragma unroll
            for (int m = 0; m < 4; m++) atomicAdd(&srow[iloc + m], rowloc[m]);
        }

        // block-level reduce ssf -> private partial slot (NO global atomic)
        double ss = (double)ssf;
#pragma unroll
        for (int off = 16; off > 0; off >>= 1)
            ss += __shfl_xor_sync(0xffffffffu, ss, off);
        if (lane == 0) {
            sRed[w][0] = 0.0; sRed[w][1] = 0.0; sRed[w][2] = 0.0;
            sRed[w][3] = 0.0; sRed[w][4] = 0.0; sRed[w][5] = ss;
        }
        __syncthreads();
        if (tid == 0) {
            double tot = 0.0;
#pragma unroll
            for (int q = 0; q < 8; q++) tot += sRed[q][5];
            g_part[b][0] = 0.0; g_part[b][1] = 0.0; g_part[b][2] = 0.0;
            g_part[b][3] = 0.0; g_part[b][4] = 0.0; g_part[b][5] = tot;
        }
        int st = b & 7;
        if (tid < 64) {
            atomicAdd(&g_colAs[st][bj * 64 + tid], scol[tid]);
            if (!diag) atomicAdd(&g_colAs[st][bi * 64 + tid], srow[tid]);
        }
    } else {
        // ================= realDist block: 8 i-rows x 512 j =================
        int rb = b - NTRI;
        int i0 = (rb >> 1) * 8;

        // hoist both j indexes (independent loads, early issue)
        int jg0 = (rb & 1) * 512 + tid;
        int jg1 = jg0 + 256;
        int idxjA = __ldg(idI + jg0);
        int idxjB = __ldg(idI + jg1);

        if (tid < 128) {
            int ii = tid >> 4, d = tid & 15;
            int idxi = __ldg(idI + i0 + ii);
            float cl = __ldg(child + (size_t)idxi * 32 + d);
            float ch = __ldg(child + (size_t)idxi * 32 + 16 + d);
            sI[ii][d]      = cl;
            sI[ii][16 + d] = ch;
            sI[ii][32 + d] = 1.0f / fmaxf(ch - cl, EPSF);
        }
        int idxi8[8];
#pragma unroll
        for (int ii = 0; ii < 8; ii++) idxi8[ii] = __ldg(idI + i0 + ii);
        __syncthreads();

        double ssq = 0.0, ovd = 0.0;
        double eAcc = 0.0, shAcc = 0.0, poAcc = 0.0;
        bool doPrep = (rb < 2);
        int st = (rb >> 1) & 7;

#pragma unroll
        for (int q = 0; q < 2; q++) {
            int jglob = q ? jg1 : jg0;
            int idxj  = q ? idxjB : idxjA;

            // prefetch gathers (MLP=8)
            float acc[8];
#pragma unroll
            for (int ii = 0; ii < 8; ii++)
                acc[ii] = __ldg(layerDist + (size_t)idxi8[ii] * Cc + idxj);

            float4 lj[4], hj[4];
            const float4* pl = (const float4*)(child + (size_t)idxj * 32);
            const float4* ph = (const float4*)(child + (size_t)idxj * 32 + 16);
#pragma unroll
            for (int u = 0; u < 4; u++) { lj[u] = pl[u]; hj[u] = ph[u]; }

            float colsum = 0.f, ssqf = 0.f, ovf = 0.f;
#pragma unroll
            for (int ii = 0; ii < 8; ii++) {
                const float4* iL = (const float4*)&sI[ii][0];
                const float4* iH = (const float4*)&sI[ii][16];
                const float4* iV = (const float4*)&sI[ii][32];
                float cd = 0.f, o = 0.f;
#pragma unroll
                for (int u = 0; u < 4; u++) {
                    float4 a = iL[u], bb = iH[u], v = iV[u];
                    float4 l = lj[u], h = hj[u];
                    cd += fabsf(a.x - l.x) + fabsf(a.y - l.y)
                        + fabsf(a.z - l.z) + fabsf(a.w - l.w);
                    o += fmaxf(fminf(bb.x, h.x) - fmaxf(a.x, l.x), 0.f) * v.x;
                    o += fmaxf(fminf(bb.y, h.y) - fmaxf(a.y, l.y), 0.f) * v.y;
                    o += fmaxf(fminf(bb.z, h.z) - fmaxf(a.z, l.z), 0.f) * v.z;
                    o += fmaxf(fminf(bb.w, h.w) - fmaxf(a.w, l.w), 0.f) * v.w;
                }
                float r = acc[ii] + cd;
                colsum += r;
                ssqf += r * r;
                if (i0 + ii != jglob) ovf += o;
            }
            atomicAdd(&g_colRs[st][jglob], colsum);
            ssq += (double)ssqf;
            ovd += (double)ovf;

            // ---- fused per-node prep (blocks rb=0,1 cover all nodes) ----
            if (doPrep) {
                int p = __ldg(par + jglob);
                float leaf = __ldg(leaves + idxj);
                const float HPI = (float)(3.14159265358979323846 * 0.5);
                const float CAP = (float)(3.14159265358979323846 * 0.49999);
                const float4* prl = (const float4*)(resv + (size_t)p * 32);
                const float4* prh = (const float4*)(resv + (size_t)p * 32 + 16);
                float exceed = 0.f, shape = 0.f, pos = 0.f;
#pragma unroll
                for (int u = 0; u < 4; u++) {
                    float4 cl = lj[u], ch = hj[u];
                    float4 rl = prl[u], rh = prh[u];
                    float cc[4] = {cl.x, cl.y, cl.z, cl.w};
                    float ee[4] = {ch.x, ch.y, ch.z, ch.w};
                    float aa[4] = {rl.x, rl.y, rl.z, rl.w};
                    float zz[4] = {rh.x, rh.y, rh.z, rh.w};
#pragma unroll
                    for (int d = 0; d < 4; d++) {
                        float diff = ee[d] - cc[d];
                        exceed += fmaxf((aa[d] + 1.0f) - cc[d], 0.f)
                                + fmaxf(ee[d] - (zz[d] + 1.0f), 0.f);
                        float numer = fmaxf(diff / (zz[d] - aa[d]), EPSF);
                        float sdiv  = fminf(numer / leaf, CAP);
                        shape += fminf(fabsf(tanf((sdiv - 1.0f) * HPI)), CLIPMAXF);
                        pos += fmaxf(expf(-diff), EPSF);
                    }
                }
                eAcc += (double)exceed; shAcc += (double)shape; poAcc += (double)pos;
            }
        }

        // block-level reduce -> private partial slot (NO global double atomics)
#pragma unroll
        for (int off = 16; off > 0; off >>= 1) {
            ssq   += __shfl_xor_sync(0xffffffffu, ssq,   off);
            ovd   += __shfl_xor_sync(0xffffffffu, ovd,   off);
            eAcc  += __shfl_xor_sync(0xffffffffu, eAcc,  off);
            shAcc += __shfl_xor_sync(0xffffffffu, shAcc, off);
            poAcc += __shfl_xor_sync(0xffffffffu, poAcc, off);
        }
        if (lane == 0) {
            sRed[w][0] = ssq;  sRed[w][1] = ovd;  sRed[w][2] = eAcc;
            sRed[w][3] = shAcc; sRed[w][4] = poAcc; sRed[w][5] = 0.0;
        }
        __syncthreads();
        if (tid == 0) {
            double t0 = 0.0, t1 = 0.0, t2 = 0.0, t3 = 0.0, t4 = 0.0;
#pragma unroll
            for (int q = 0; q < 8; q++) {
                t0 += sRed[q][0]; t1 += sRed[q][1]; t2 += sRed[q][2];
                t3 += sRed[q][3]; t4 += sRed[q][4];
            }
            g_part[b][0] = t0; g_part[b][1] = t1; g_part[b][2] = t2;
            g_part[b][3] = t3; g_part[b][4] = t4; g_part[b][5] = 0.0;
        }
    }

    // ================= last-block finalize + state re-zero =================
    __threadfence();
    if (tid == 0) isLast = (atomicAdd(&g_done, 1u) == NTOT - 1);
    __syncthreads();
    if (!isLast) return;
    __threadfence();

    // sum scalar partials across all blocks
    double p0 = 0.0, p1 = 0.0, p2 = 0.0, p3 = 0.0, p4 = 0.0, p5 = 0.0;
    for (int q = tid; q < NTOT; q += 256) {
        p0 += __ldcg(&g_part[q][0]); p1 += __ldcg(&g_part[q][1]);
        p2 += __ldcg(&g_part[q][2]); p3 += __ldcg(&g_part[q][3]);
        p4 += __ldcg(&g_part[q][4]); p5 += __ldcg(&g_part[q][5]);
    }
#pragma unroll
    for (int off = 16; off > 0; off >>= 1) {
        p0 += __shfl_xor_sync(0xffffffffu, p0, off);
        p1 += __shfl_xor_sync(0xffffffffu, p1, off);
        p2 += __shfl_xor_sync(0xffffffffu, p2, off);
        p3 += __shfl_xor_sync(0xffffffffu, p3, off);
        p4 += __shfl_xor_sync(0xffffffffu, p4, off);
        p5 += __shfl_xor_sync(0xffffffffu, p5, off);
    }
    if (lane == 0) {
        sRed[w][0] = p0; sRed[w][1] = p1; sRed[w][2] = p2;
        sRed[w][3] = p3; sRed[w][4] = p4; sRed[w][5] = p5;
    }

    // col sums: de-stripe, accumulate s1 = sum(colR*colA), s2 = sum(colR^2)
    double s1 = 0.0, s2 = 0.0;
#pragma unroll
    for (int q = 0; q < 4; q++) {
        int j = tid + q * 256;
        float r = 0.f, a = 0.f;
#pragma unroll
        for (int s = 0; s < 8; s++) {
            r += __ldcg(&g_colRs[s][j]);
            a += __ldcg(&g_colAs[s][j]);
            g_colRs[s][j] = 0.f;
            g_colAs[s][j] = 0.f;
        }
        s1 += (double)r * (double)a;
        s2 += (double)r * (double)r;
    }
    __shared__ double r1[8], r2[8];
#pragma unroll
    for (int off = 16; off > 0; off >>= 1) {
        s1 += __shfl_xor_sync(0xffffffffu, s1, off);
        s2 += __shfl_xor_sync(0xffffffffu, s2, off);
    }
    if (lane == 0) { r1[w] = s1; r2[w] = s2; }
    __syncthreads();
    if (tid == 0) {
        double a = 0.0, cc2 = 0.0;
        double sumsqR = 0.0, ovl = 0.0, exc = 0.0, shp = 0.0, pos = 0.0, sumsqA = 0.0;
#pragma unroll
        for (int q = 0; q < 8; q++) {
            a += r1[q]; cc2 += r2[q];
            sumsqR += sRed[q][0]; ovl += sRed[q][1]; exc += sRed[q][2];
            shp += sRed[q][3]; pos += sRed[q][4]; sumsqA += sRed[q][5];
        }
        double nR = fmax(sqrt(sumsqR), 1e-15);
        double nA = fmax(sqrt(sumsqA), 1e-15);
        double val = sumsqA / (nA * nA) - 2.0 * (a / nR) / nA + (double)Nn * (cc2 / (nR * nR));
        double lossDist = sqrt(fmax(val, 0.0));
        out[0] = (float)(lossDist + shp + exc + ovl + pos);
        g_done = 0u;
    }
}

// ---------------- launch ----------------
extern "C" void kernel_launch(void* const* d_in, const int* in_sizes, int n_in,
                              void* d_out, int out_size) {
    const int*   idI    = (const int*)d_in[0];
    const int*   par    = (const int*)d_in[1];
    const float* omega  = (const float*)d_in[2];
    const float* child  = (const float*)d_in[3];
    const float* resv   = (const float*)d_in[4];
    const float* leaves = (const float*)d_in[5];
    const float* layerD = (const float*)d_in[6];
    (void)in_sizes; (void)n_in; (void)out_size;

    k_all<<<NTOT, 256>>>(idI, par, omega, child, resv, leaves, layerD, (float*)d_out);
}

// round 7
// speedup vs baseline: 1.1810x; 1.0585x over previous
#include <cuda_runtime.h>
#include <math.h>

#define Nn 1024
#define Cc 8192
#define Dd 16
#define ODim 128
#define EPSF 1e-15f
#define CLIPMAXF 10000.0f
#define NB 16                      // 1024/64 tiles per side
#define NTRI (NB*(NB+1)/2)         // 136 triangular omega tiles
#define NREAL 256                  // 64 i-chunks x 4 j-quarters
#define NTOT (NTRI + NREAL)        // 392

// ---------- state (device globals; zero at load, re-zeroed by finalize) ----------
__device__ float    g_colR[Nn];
__device__ float    g_colA[Nn];
__device__ double   g_sumsqR;
__device__ double   g_sumsqA;
__device__ double   g_overlap;
__device__ double   g_exceed;
__device__ double   g_shape;
__device__ double   g_positive;
__device__ unsigned g_done;

__global__ void __launch_bounds__(256, 4)
k_all(const int* __restrict__ idI, const int* __restrict__ par,
      const float* __restrict__ omega, const float* __restrict__ child,
      const float* __restrict__ resv, const float* __restrict__ leaves,
      const float* __restrict__ layerDist, float* __restrict__ out) {
    __shared__ float sA[2][32][64];
    __shared__ float sB[2][32][64];
    __shared__ float sInnA[64], sInnB[64];
    __shared__ float scol[64], srow[64];
    __shared__ __align__(16) float sI[16][48];
    __shared__ int   sIdx[16];
    __shared__ bool isLast;

    int tid = threadIdx.x;
    int w = tid >> 5, lane = tid & 31;
    int b = blockIdx.x;

    if (b < NTRI) {
        // ============ omega tile (64x64 triangular), pipelined ============
        int t = b, bi = 0;
        while (t >= NB - bi) { t -= NB - bi; bi++; }
        int bj = bi + t;
        bool diag = (bi == bj);

        if (tid < 64) { scol[tid] = 0.f; srow[tid] = 0.f; }

        float c[4][4];
#pragma unroll
        for (int m = 0; m < 4; m++)
#pragma unroll
            for (int n = 0; n < 4; n++) c[m][n] = 0.f;

        int ri = lane >> 3;
        int cj = lane & 7;
        int iloc = (w & 3) * 16 + ri * 4;
        int jloc = (w >> 2) * 32 + cj * 4;

        // per-thread chunk-load mapping: 2 float4 for A, 2 for B
        int r0 = tid & 63,          q0 = tid >> 6;          // q0 in 0..3
        int r1 = r0,                q1 = q0 + 4;            // q in 4..7
        const float4* og4 = (const float4*)omega;
        size_t rowA = (size_t)(bi * 64) * (ODim / 4);
        size_t rowB = (size_t)(bj * 64) * (ODim / 4);

        float4 pa0, pa1, pb0, pb1;
        // prefetch chunk 0
        pa0 = og4[rowA + (size_t)r0 * (ODim / 4) + q0];
        pa1 = og4[rowA + (size_t)r1 * (ODim / 4) + q1];
        pb0 = og4[rowB + (size_t)r0 * (ODim / 4) + q0];
        pb1 = og4[rowB + (size_t)r1 * (ODim / 4) + q1];

#pragma unroll
        for (int cchunk = 0; cchunk < 4; cchunk++) {
            int cur = cchunk & 1;
            // store prefetched chunk
            sA[cur][q0 * 4 + 0][r0] = pa0.x; sA[cur][q0 * 4 + 1][r0] = pa0.y;
            sA[cur][q0 * 4 + 2][r0] = pa0.z; sA[cur][q0 * 4 + 3][r0] = pa0.w;
            sA[cur][q1 * 4 + 0][r1] = pa1.x; sA[cur][q1 * 4 + 1][r1] = pa1.y;
            sA[cur][q1 * 4 + 2][r1] = pa1.z; sA[cur][q1 * 4 + 3][r1] = pa1.w;
            sB[cur][q0 * 4 + 0][r0] = pb0.x; sB[cur][q0 * 4 + 1][r0] = pb0.y;
            sB[cur][q0 * 4 + 2][r0] = pb0.z; sB[cur][q0 * 4 + 3][r0] = pb0.w;
            sB[cur][q1 * 4 + 0][r1] = pb1.x; sB[cur][q1 * 4 + 1][r1] = pb1.y;
            sB[cur][q1 * 4 + 2][r1] = pb1.z; sB[cur][q1 * 4 + 3][r1] = pb1.w;
            __syncthreads();

            // prefetch next chunk (overlaps compute below)
            if (cchunk < 3) {
                int kq = (cchunk + 1) * 8;
                pa0 = og4[rowA + (size_t)r0 * (ODim / 4) + kq + q0];
                pa1 = og4[rowA + (size_t)r1 * (ODim / 4) + kq + q1];
                pb0 = og4[rowB + (size_t)r0 * (ODim / 4) + kq + q0];
                pb1 = og4[rowB + (size_t)r1 * (ODim / 4) + kq + q1];
            }

            // compute 32 k with register double-buffer
            float4 av = *(const float4*)&sA[cur][0][iloc];
            float4 bv = *(const float4*)&sB[cur][0][jloc];
#pragma unroll
            for (int k = 0; k < 32; k++) {
                float4 an, bn;
                if (k < 31) {
                    an = *(const float4*)&sA[cur][k + 1][iloc];
                    bn = *(const float4*)&sB[cur][k + 1][jloc];
                }
                c[0][0] += av.x * bv.x; c[0][1] += av.x * bv.y; c[0][2] += av.x * bv.z; c[0][3] += av.x * bv.w;
                c[1][0] += av.y * bv.x; c[1][1] += av.y * bv.y; c[1][2] += av.y * bv.z; c[1][3] += av.y * bv.w;
                c[2][0] += av.z * bv.x; c[2][1] += av.z * bv.y; c[2][2] += av.z * bv.z; c[2][3] += av.z * bv.w;
                c[3][0] += av.w * bv.x; c[3][1] += av.w * bv.y; c[3][2] += av.w * bv.z; c[3][3] += av.w * bv.w;
                if (k < 31) { av = an; bv = bn; }
            }
        }

        // inner norms for this tile's rows/cols (L2-hot)
        if (tid < 128) {
            int r = tid & 63;
            int row = ((tid < 64) ? bi : bj) * 64 + r;
            const float4* p = (const float4*)(omega + (size_t)row * ODim);
            float s0 = 0.f, s1 = 0.f;
#pragma unroll
            for (int q = 0; q < ODim / 8; q++) {
                float4 v = p[2 * q], u = p[2 * q + 1];
                s0 += v.x * v.x + v.y * v.y + v.z * v.z + v.w * v.w;
                s1 += u.x * u.x + u.y * u.y + u.z * u.z + u.w * u.w;
            }
            if (tid < 64) sInnA[r] = s0 + s1; else sInnB[r] = s0 + s1;
        }
        __syncthreads();

        float innI[4], innJ[4];
#pragma unroll
        for (int m = 0; m < 4; m++) innI[m] = sInnA[iloc + m];
#pragma unroll
        for (int n = 0; n < 4; n++) innJ[n] = sInnB[jloc + n];

        float colloc[4] = {0.f, 0.f, 0.f, 0.f};
        float rowloc[4] = {0.f, 0.f, 0.f, 0.f};
        float ssf = 0.f;
#pragma unroll
        for (int m = 0; m < 4; m++)
#pragma unroll
            for (int n = 0; n < 4; n++) {
                float a = fmaxf(innI[m] + innJ[n] - 2.0f * c[m][n], EPSF);
                ssf += a * a;
                colloc[n] += a;
                rowloc[m] += a;
            }
        if (!diag) ssf *= 2.0f;

#pragma unroll
        for (int n = 0; n < 4; n++) atomicAdd(&scol[jloc + n], colloc[n]);
        if (!diag) {
#pragma unroll
            for (int m = 0; m < 4; m++) atomicAdd(&srow[iloc + m], rowloc[m]);
        }

        double ss = (double)ssf;
#pragma unroll
        for (int off = 16; off > 0; off >>= 1)
            ss += __shfl_xor_sync(0xffffffffu, ss, off);
        if (lane == 0) atomicAdd(&g_sumsqA, ss);

        __syncthreads();
        if (tid < 64) {
            atomicAdd(&g_colA[bj * 64 + tid], scol[tid]);
            if (!diag) atomicAdd(&g_colA[bi * 64 + tid], srow[tid]);
        }
    } else {
        // ============ realDist block: 16 i-rows x 256 j, pipelined ============
        int rb = b - NTRI;
        int i0 = (rb >> 2) * 16;
        int jglob = (rb & 3) * 256 + tid;

        int idxj = __ldg(idI + jglob);

        {   // stage i-side data: 16 rows x 16 dims = 256 entries, one per thread
            int ii = tid >> 4, d = tid & 15;
            int idxi = __ldg(idI + i0 + ii);
            if (d == 0) sIdx[ii] = idxi;
            float cl = __ldg(child + (size_t)idxi * 32 + d);
            float ch = __ldg(child + (size_t)idxi * 32 + 16 + d);
            sI[ii][d]      = cl;
            sI[ii][16 + d] = ch;
            sI[ii][32 + d] = 1.0f / fmaxf(ch - cl, EPSF);
        }

        // j-side data (L2-hot gather)
        float4 lj[4], hj[4];
        const float4* pl = (const float4*)(child + (size_t)idxj * 32);
        const float4* ph = (const float4*)(child + (size_t)idxj * 32 + 16);
#pragma unroll
        for (int u = 0; u < 4; u++) { lj[u] = pl[u]; hj[u] = ph[u]; }
        __syncthreads();

        // gather batch A (ii 0..7)
        float accA[8];
#pragma unroll
        for (int ii = 0; ii < 8; ii++)
            accA[ii] = __ldg(layerDist + (size_t)sIdx[ii] * Cc + idxj);
        // gather batch B (ii 8..15) — in flight while computing batch A
        float accB[8];
#pragma unroll
        for (int ii = 0; ii < 8; ii++)
            accB[ii] = __ldg(layerDist + (size_t)sIdx[8 + ii] * Cc + idxj);

        float colsum0 = 0.f, colsum1 = 0.f, ssqf0 = 0.f, ssqf1 = 0.f;
        float ovf0 = 0.f, ovf1 = 0.f;
#pragma unroll
        for (int ii = 0; ii < 16; ii++) {
            const float4* iL = (const float4*)&sI[ii][0];
            const float4* iH = (const float4*)&sI[ii][16];
            const float4* iV = (const float4*)&sI[ii][32];
            float cd0 = 0.f, cd1 = 0.f, o0 = 0.f, o1 = 0.f;
#pragma unroll
            for (int u = 0; u < 4; u++) {
                float4 a = iL[u], bb = iH[u], v = iV[u];
                float4 l = lj[u], h = hj[u];
                float cdp = fabsf(a.x - l.x) + fabsf(a.y - l.y)
                          + fabsf(a.z - l.z) + fabsf(a.w - l.w);
                float op = fmaxf(fminf(bb.x, h.x) - fmaxf(a.x, l.x), 0.f) * v.x
                         + fmaxf(fminf(bb.y, h.y) - fmaxf(a.y, l.y), 0.f) * v.y
                         + fmaxf(fminf(bb.z, h.z) - fmaxf(a.z, l.z), 0.f) * v.z
                         + fmaxf(fminf(bb.w, h.w) - fmaxf(a.w, l.w), 0.f) * v.w;
                if (u & 1) { cd1 += cdp; o1 += op; }
                else       { cd0 += cdp; o0 += op; }
            }
            float r = ((ii < 8) ? accA[ii & 7] : accB[ii & 7]) + (cd0 + cd1);
            float o = o0 + o1;
            if (ii & 1) { colsum1 += r; ssqf1 += r * r; }
            else        { colsum0 += r; ssqf0 += r * r; }
            if (i0 + ii != jglob) { if (ii & 1) ovf1 += o; else ovf0 += o; }
        }
        atomicAdd(&g_colR[jglob], colsum0 + colsum1);

        double ssq = (double)(ssqf0 + ssqf1);
        double ovd = (double)(ovf0 + ovf1);
#pragma unroll
        for (int off = 16; off > 0; off >>= 1) {
            ssq += __shfl_xor_sync(0xffffffffu, ssq, off);
            ovd += __shfl_xor_sync(0xffffffffu, ovd, off);
        }
        if (lane == 0) {
            atomicAdd(&g_sumsqR, ssq);
            atomicAdd(&g_overlap, ovd);
        }

        // ---- fused per-node prep (blocks rb=0..3 cover all 1024 nodes) ----
        if (rb < 4) {
            int p = __ldg(par + jglob);
            float leaf = __ldg(leaves + idxj);
            const float HPI = (float)(3.14159265358979323846 * 0.5);
            const float CAP = (float)(3.14159265358979323846 * 0.49999);
            const float4* prl = (const float4*)(resv + (size_t)p * 32);
            const float4* prh = (const float4*)(resv + (size_t)p * 32 + 16);
            float exceed = 0.f, shape = 0.f, pos = 0.f;
#pragma unroll
            for (int u = 0; u < 4; u++) {
                float4 cl = lj[u], ch = hj[u];
                float4 rl = prl[u], rh = prh[u];
                float cc[4] = {cl.x, cl.y, cl.z, cl.w};
                float ee[4] = {ch.x, ch.y, ch.z, ch.w};
                float aa[4] = {rl.x, rl.y, rl.z, rl.w};
                float zz[4] = {rh.x, rh.y, rh.z, rh.w};
#pragma unroll
                for (int d = 0; d < 4; d++) {
                    float diff = ee[d] - cc[d];
                    exceed += fmaxf((aa[d] + 1.0f) - cc[d], 0.f)
                            + fmaxf(ee[d] - (zz[d] + 1.0f), 0.f);
                    float numer = fmaxf(diff / (zz[d] - aa[d]), EPSF);
                    float sdiv  = fminf(numer / leaf, CAP);
                    shape += fminf(fabsf(tanf((sdiv - 1.0f) * HPI)), CLIPMAXF);
                    pos += fmaxf(expf(-diff), EPSF);
                }
            }
            double e = (double)exceed, sh = (double)shape, po = (double)pos;
#pragma unroll
            for (int off = 16; off > 0; off >>= 1) {
                e  += __shfl_xor_sync(0xffffffffu, e,  off);
                sh += __shfl_xor_sync(0xffffffffu, sh, off);
                po += __shfl_xor_sync(0xffffffffu, po, off);
            }
            if (lane == 0) {
                atomicAdd(&g_exceed,   e);
                atomicAdd(&g_shape,    sh);
                atomicAdd(&g_positive, po);
            }
        }
    }

    // ================= last-block finalize + state re-zero =================
    __threadfence();
    if (tid == 0) isLast = (atomicAdd(&g_done, 1u) == NTOT - 1);
    __syncthreads();
    if (!isLast) return;
    __threadfence();

    double s1 = 0.0, s2 = 0.0;
#pragma unroll
    for (int q = 0; q < 4; q++) {
        int j = tid + q * 256;
        double r = (double)__ldcg(&g_colR[j]);
        double a = (double)__ldcg(&g_colA[j]);
        s1 += r * a;
        s2 += r * r;
        g_colR[j] = 0.f;
        g_colA[j] = 0.f;
    }
    __shared__ double r1[8], r2[8];
#pragma unroll
    for (int off = 16; off > 0; off >>= 1) {
        s1 += __shfl_xor_sync(0xffffffffu, s1, off);
        s2 += __shfl_xor_sync(0xffffffffu, s2, off);
    }
    if (lane == 0) { r1[w] = s1; r2[w] = s2; }
    __syncthreads();
    if (tid == 0) {
        double a = 0.0, cc2 = 0.0;
#pragma unroll
        for (int q = 0; q < 8; q++) { a += r1[q]; cc2 += r2[q]; }
        double sumsqR = __ldcg(&g_sumsqR);
        double sumsqA = __ldcg(&g_sumsqA);
        double nR = fmax(sqrt(sumsqR), 1e-15);
        double nA = fmax(sqrt(sumsqA), 1e-15);
        double val = sumsqA / (nA * nA) - 2.0 * (a / nR) / nA + (double)Nn * (cc2 / (nR * nR));
        double lossDist = sqrt(fmax(val, 0.0));
        out[0] = (float)(lossDist + __ldcg(&g_shape) + __ldcg(&g_exceed)
                         + __ldcg(&g_overlap) + __ldcg(&g_positive));
        g_sumsqR = 0.0; g_sumsqA = 0.0; g_overlap = 0.0;
        g_exceed = 0.0; g_shape = 0.0; g_positive = 0.0;
        g_done = 0u;
    }
}

// ---------------- launch ----------------
extern "C" void kernel_launch(void* const* d_in, const int* in_sizes, int n_in,
                              void* d_out, int out_size) {
    const int*   idI    = (const int*)d_in[0];
    const int*   par    = (const int*)d_in[1];
    const float* omega  = (const float*)d_in[2];
    const float* child  = (const float*)d_in[3];
    const float* resv   = (const float*)d_in[4];
    const float* leaves = (const float*)d_in[5];
    const float* layerD = (const float*)d_in[6];
    (void)in_sizes; (void)n_in; (void)out_size;

    k_all<<<NTOT, 256>>>(idI, par, omega, child, resv, leaves, layerD, (float*)d_out);
}

// round 8
// speedup vs baseline: 1.2617x; 1.0684x over previous
#include <cuda_runtime.h>
#include <math.h>

#define Nn 1024
#define Cc 8192
#define ODim 128
#define EPSF 1e-15f
#define CLIPMAXF 10000.0f
#define NB 16
#define NPAIR 272                  // 136 triangular 64x64 tiles x 2 j-halves
#define NG 48                      // 3 Gram tiles x 16 K-chunks
#define NS 8                       // s/inner/t blocks
#define NTOT (NPAIR + NG + NS)     // 328

// ---------- device state (zero at load; restored each run) ----------
__device__ float    g_colR[Nn];          // atomics; re-zeroed by finalize
__device__ float    g_inner[Nn];         // overwritten
__device__ float    g_t[Nn];             // overwritten
__device__ float    g_sPart[16][ODim];   // overwritten
__device__ float    g_G[3][4096];        // atomics; re-zeroed by last G-block
__device__ double   g_normG;             // overwritten
__device__ double   g_sumsqR, g_overlap, g_exceed, g_shape, g_positive;
__device__ unsigned g_done, g_doneS, g_doneG;

__global__ void __launch_bounds__(256)
k_all(const int* __restrict__ idI, const int* __restrict__ par,
      const float* __restrict__ omega, const float* __restrict__ child,
      const float* __restrict__ resv, const float* __restrict__ leaves,
      const float* __restrict__ layerDist, float* __restrict__ out)
{
    __shared__ __align__(16) char sm[33024];
    __shared__ bool isLast;
    int tid = threadIdx.x, w = tid >> 5, lane = tid & 31;
    int b = blockIdx.x;

    if (b < NPAIR) {
        // ========== symmetric realdist: tile (bi<=bj) 64 i x 32 j ==========
        float (*sI)[48] = (float(*)[48])sm;
        int* sIdxI = (int*)(sm + 64 * 48 * 4);
        int t = b >> 1, h = b & 1, bi = 0;
        while (t >= NB - bi) { t -= NB - bi; bi++; }
        int bj = bi + t;
        int I0 = bi * 64, J0 = bj * 64 + h * 32;

        if (tid < 64) sIdxI[tid] = __ldg(idI + I0 + tid);

        int jglob = J0 + lane;
        int idxj = __ldg(idI + jglob);
        float4 lj[4], hj[4], vj[4];
        {
            const float4* pl = (const float4*)(child + (size_t)idxj * 32);
            const float4* ph = (const float4*)(child + (size_t)idxj * 32 + 16);
#pragma unroll
            for (int u = 0; u < 4; u++) {
                lj[u] = pl[u]; hj[u] = ph[u];
                vj[u].x = 1.0f / fmaxf(hj[u].x - lj[u].x, EPSF);
                vj[u].y = 1.0f / fmaxf(hj[u].y - lj[u].y, EPSF);
                vj[u].z = 1.0f / fmaxf(hj[u].z - lj[u].z, EPSF);
                vj[u].w = 1.0f / fmaxf(hj[u].w - lj[u].w, EPSF);
            }
        }
        __syncthreads();

        for (int e = tid; e < 64 * 16; e += 256) {
            int ii = e >> 4, d = e & 15;
            int ix = sIdxI[ii];
            float cl = __ldg(child + (size_t)ix * 32 + d);
            float ch = __ldg(child + (size_t)ix * 32 + 16 + d);
            sI[ii][d] = cl; sI[ii][16 + d] = ch;
            sI[ii][32 + d] = 1.0f / fmaxf(ch - cl, EPSF);
        }
        // gathers: both orders for this warp's 8 i-rows (MLP=16)
        float aij[8], aji[8];
        int ibase = I0 + w * 8;
#pragma unroll
        for (int k = 0; k < 8; k++) {
            int ix = sIdxI[w * 8 + k];
            aij[k] = __ldg(layerDist + (size_t)ix * Cc + idxj);
            aji[k] = __ldg(layerDist + (size_t)idxj * Cc + ix);
        }
        __syncthreads();

        float colsumJ = 0.f;
        double ssq = 0.0, ovd = 0.0;
#pragma unroll
        for (int k = 0; k < 8; k++) {
            int ig = ibase + k;
            const float4* iL = (const float4*)&sI[w * 8 + k][0];
            const float4* iH = (const float4*)&sI[w * 8 + k][16];
            const float4* iV = (const float4*)&sI[w * 8 + k][32];
            float cd = 0.f, ov = 0.f;
#pragma unroll
            for (int u = 0; u < 4; u++) {
                float4 a = iL[u], bb = iH[u], vi = iV[u];
                float4 l = lj[u], hh = hj[u], v2 = vj[u];
                cd += fabsf(a.x - l.x) + fabsf(a.y - l.y)
                    + fabsf(a.z - l.z) + fabsf(a.w - l.w);
                float nx = fmaxf(fminf(bb.x, hh.x) - fmaxf(a.x, l.x), 0.f);
                float ny = fmaxf(fminf(bb.y, hh.y) - fmaxf(a.y, l.y), 0.f);
                float nz = fmaxf(fminf(bb.z, hh.z) - fmaxf(a.z, l.z), 0.f);
                float nw = fmaxf(fminf(bb.w, hh.w) - fmaxf(a.w, l.w), 0.f);
                ov += nx * (vi.x + v2.x) + ny * (vi.y + v2.y)
                    + nz * (vi.z + v2.z) + nw * (vi.w + v2.w);
            }
            float r1 = aij[k] + cd;   // realDist[i][j] -> colR[j]
            float r2 = aji[k] + cd;   // realDist[j][i] -> colR[i]
            float wv = 0.f;
            if (ig < jglob) {
                colsumJ += r1;
                ssq += (double)(r1 * r1 + r2 * r2);
                ovd += (double)ov;
                wv = r2;
            } else if (ig == jglob) {
                colsumJ += r1;                       // cd==0 -> acc_ii
                ssq += (double)(r1 * r1);
            }
#pragma unroll
            for (int o = 16; o > 0; o >>= 1) wv += __shfl_xor_sync(0xffffffffu, wv, o);
            if (lane == 0 && wv != 0.f) atomicAdd(&g_colR[ig], wv);
        }
        atomicAdd(&g_colR[jglob], colsumJ);

#pragma unroll
        for (int o = 16; o > 0; o >>= 1) {
            ssq += __shfl_xor_sync(0xffffffffu, ssq, o);
            ovd += __shfl_xor_sync(0xffffffffu, ovd, o);
        }
        if (lane == 0) {
            atomicAdd(&g_sumsqR, ssq);
            atomicAdd(&g_overlap, ovd);
        }

        // ---- per-node prep: blocks with bi==0 (b<32), warp 0, lane's j ----
        if (b < 32 && w == 0) {
            int p = __ldg(par + jglob);
            float leaf = __ldg(leaves + idxj);
            const float HPI = (float)(3.14159265358979323846 * 0.5);
            const float CAP = (float)(3.14159265358979323846 * 0.49999);
            const float4* prl = (const float4*)(resv + (size_t)p * 32);
            const float4* prh = (const float4*)(resv + (size_t)p * 32 + 16);
            float exceed = 0.f, shape = 0.f, pos = 0.f;
#pragma unroll
            for (int u = 0; u < 4; u++) {
                float4 cl = lj[u], ch = hj[u];
                float4 rl = prl[u], rh = prh[u];
                float cc[4] = {cl.x, cl.y, cl.z, cl.w};
                float ee[4] = {ch.x, ch.y, ch.z, ch.w};
                float aa[4] = {rl.x, rl.y, rl.z, rl.w};
                float zz[4] = {rh.x, rh.y, rh.z, rh.w};
#pragma unroll
                for (int d = 0; d < 4; d++) {
                    float diff = ee[d] - cc[d];
                    exceed += fmaxf((aa[d] + 1.0f) - cc[d], 0.f)
                            + fmaxf(ee[d] - (zz[d] + 1.0f), 0.f);
                    float numer = fmaxf(diff / (zz[d] - aa[d]), EPSF);
                    float sdiv  = fminf(numer / leaf, CAP);
                    shape += fminf(fabsf(tanf((sdiv - 1.0f) * HPI)), CLIPMAXF);
                    pos += fmaxf(expf(-diff), EPSF);
                }
            }
            double e = exceed, sh = shape, po = pos;
#pragma unroll
            for (int o = 16; o > 0; o >>= 1) {
                e  += __shfl_xor_sync(0xffffffffu, e,  o);
                sh += __shfl_xor_sync(0xffffffffu, sh, o);
                po += __shfl_xor_sync(0xffffffffu, po, o);
            }
            if (lane == 0) {
                atomicAdd(&g_exceed, e);
                atomicAdd(&g_shape, sh);
                atomicAdd(&g_positive, po);
            }
        }
    } else if (b < NPAIR + NG) {
        // ========== Gram: G = O^T O, tile g in {(0,0),(0,64),(64,64)}, K-chunk kc ==========
        float (*sO)[ODim] = (float(*)[ODim])sm;
        int gb = b - NPAIR;
        int g = gb >> 4, kc = gb & 15;
        int P0 = (g == 2) ? 64 : 0;
        int Q0 = (g == 0) ? 0 : 64;

        const float4* og4 = (const float4*)(omega + (size_t)kc * 64 * ODim);
        for (int e = tid; e < 64 * 32; e += 256) ((float4*)sO)[e] = og4[e];
        __syncthreads();

        int pl_ = ((tid >> 4) & 15) * 4, ql_ = (tid & 15) * 4;
        float c[4][4];
#pragma unroll
        for (int m = 0; m < 4; m++)
#pragma unroll
            for (int n = 0; n < 4; n++) c[m][n] = 0.f;
#pragma unroll 8
        for (int k = 0; k < 64; k++) {
            float4 a  = *(const float4*)&sO[k][P0 + pl_];
            float4 bb = *(const float4*)&sO[k][Q0 + ql_];
            c[0][0] += a.x * bb.x; c[0][1] += a.x * bb.y; c[0][2] += a.x * bb.z; c[0][3] += a.x * bb.w;
            c[1][0] += a.y * bb.x; c[1][1] += a.y * bb.y; c[1][2] += a.y * bb.z; c[1][3] += a.y * bb.w;
            c[2][0] += a.z * bb.x; c[2][1] += a.z * bb.y; c[2][2] += a.z * bb.z; c[2][3] += a.z * bb.w;
            c[3][0] += a.w * bb.x; c[3][1] += a.w * bb.y; c[3][2] += a.w * bb.z; c[3][3] += a.w * bb.w;
        }
#pragma unroll
        for (int m = 0; m < 4; m++)
#pragma unroll
            for (int n = 0; n < 4; n++)
                atomicAdd(&g_G[g][(pl_ + m) * 64 + ql_ + n], c[m][n]);

        __threadfence();
        __shared__ bool lastG;
        if (tid == 0) lastG = (atomicAdd(&g_doneG, 1u) == NG - 1);
        __syncthreads();
        if (lastG) {
            __threadfence();
            double acc = 0.0;
            for (int e = tid; e < 3 * 4096; e += 256) {
                int gg = e >> 12, idx = e & 4095;
                float v = __ldcg(&g_G[gg][idx]);
                g_G[gg][idx] = 0.f;            // restore for next run
                double d2 = (double)v * (double)v;
                acc += (gg == 1) ? 2.0 * d2 : d2;
            }
#pragma unroll
            for (int o = 16; o > 0; o >>= 1) acc += __shfl_xor_sync(0xffffffffu, acc, o);
            double* sR = (double*)sm;          // sO dead; resynced below
            __syncthreads();
            if (lane == 0) sR[w] = acc;
            __syncthreads();
            if (tid == 0) {
                double tot = 0.0;
#pragma unroll
                for (int q = 0; q < 8; q++) tot += sR[q];
                g_normG = tot;
            }
        }
    } else {
        // ========== s / inner / t blocks ==========
        int sb = b - NPAIR - NG;
        int base = sb * 128;
        int half = tid & 1;
        // inner_i for 128 rows (2 threads per row)
        {
            int row = base + (tid >> 1);
            const float4* p = (const float4*)(omega + (size_t)row * ODim + half * 64);
            float s = 0.f;
#pragma unroll
            for (int q = 0; q < 16; q++) {
                float4 v = p[q];
                s += v.x * v.x + v.y * v.y + v.z * v.z + v.w * v.w;
            }
            float o = __shfl_xor_sync(0xffffffffu, s, 1);
            if (half == 0) g_inner[row] = s + o;
        }
        // s partial: column sums over 64 rows
        {
            int d = tid & 127, rh = tid >> 7;
            float sp = 0.f;
            for (int r = 0; r < 64; r++)
                sp += __ldg(omega + (size_t)(base + rh * 64 + r) * ODim + d);
            g_sPart[sb * 2 + rh][d] = sp;
        }
        __threadfence();
        __syncthreads();
        if (tid == 0) {
            atomicAdd(&g_doneS, 1u);
            volatile unsigned* ds = &g_doneS;
            while (*ds < NS) { }
        }
        __syncthreads();
        __threadfence();
        // stage full s
        float* sS = (float*)sm;
        if (tid < ODim) {
            float s2 = 0.f;
#pragma unroll
            for (int q = 0; q < 16; q++) s2 += __ldcg(&g_sPart[q][tid]);
            sS[tid] = s2;
        }
        __syncthreads();
        // t_j = o_j . s for 128 j's
        {
            int j = base + (tid >> 1);
            const float4* oj = (const float4*)(omega + (size_t)j * ODim + half * 64);
            const float4* s4 = (const float4*)(sS + half * 64);
            float tv = 0.f;
#pragma unroll
            for (int q = 0; q < 16; q++) {
                float4 a = oj[q], s = s4[q];
                tv += a.x * s.x + a.y * s.y + a.z * s.z + a.w * s.w;
            }
            float ot = __shfl_xor_sync(0xffffffffu, tv, 1);
            if (half == 0) g_t[j] = tv + ot;
        }
    }

    // ================= last-block finalize + state restore =================
    __threadfence();
    if (tid == 0) isLast = (atomicAdd(&g_done, 1u) == NTOT - 1);
    __syncthreads();
    if (!isLast) return;
    __threadfence();

    double S1 = 0, S2 = 0, T1 = 0, CR = 0, CRI = 0, CRT = 0, s2a = 0;
#pragma unroll
    for (int q = 0; q < 4; q++) {
        int j = tid + q * 256;
        double inn = (double)__ldcg(&g_inner[j]);
        double tj  = (double)__ldcg(&g_t[j]);
        double cr  = (double)__ldcg(&g_colR[j]);
        g_colR[j] = 0.f;
        S1 += inn; S2 += inn * inn; T1 += inn * tj;
        CR += cr; CRI += cr * inn; CRT += cr * tj; s2a += cr * cr;
    }
#pragma unroll
    for (int o = 16; o > 0; o >>= 1) {
        S1 += __shfl_xor_sync(0xffffffffu, S1, o);
        S2 += __shfl_xor_sync(0xffffffffu, S2, o);
        T1 += __shfl_xor_sync(0xffffffffu, T1, o);
        CR += __shfl_xor_sync(0xffffffffu, CR, o);
        CRI += __shfl_xor_sync(0xffffffffu, CRI, o);
        CRT += __shfl_xor_sync(0xffffffffu, CRT, o);
        s2a += __shfl_xor_sync(0xffffffffu, s2a, o);
    }
    double* sR = (double*)sm;
    if (lane == 0) {
        sR[w * 7 + 0] = S1; sR[w * 7 + 1] = S2; sR[w * 7 + 2] = T1;
        sR[w * 7 + 3] = CR; sR[w * 7 + 4] = CRI; sR[w * 7 + 5] = CRT;
        sR[w * 7 + 6] = s2a;
    }
    __syncthreads();
    if (tid == 0) {
        double a0 = 0, a1 = 0, a2 = 0, a3 = 0, a4 = 0, a5 = 0, a6 = 0;
#pragma unroll
        for (int q = 0; q < 8; q++) {
            a0 += sR[q * 7 + 0]; a1 += sR[q * 7 + 1]; a2 += sR[q * 7 + 2];
            a3 += sR[q * 7 + 3]; a4 += sR[q * 7 + 4]; a5 += sR[q * 7 + 5];
            a6 += sR[q * 7 + 6];
        }
        double sumsqA = 2.0 * Nn * a1 + 2.0 * a0 * a0 - 8.0 * a2 + 4.0 * __ldcg(&g_normG);
        double s1 = a0 * a3 + (double)Nn * a4 - 2.0 * a5 + (double)EPSF * a3;
        double sumsqR = __ldcg(&g_sumsqR);
        double nR = fmax(sqrt(sumsqR), 1e-15);
        double nA = fmax(sqrt(fmax(sumsqA, 0.0)), 1e-15);
        double val = sumsqA / (nA * nA) - 2.0 * (s1 / nR) / nA + (double)Nn * (a6 / (nR * nR));
        double lossDist = sqrt(fmax(val, 0.0));
        out[0] = (float)(lossDist + __ldcg(&g_shape) + __ldcg(&g_exceed)
                         + __ldcg(&g_overlap) + __ldcg(&g_positive));
        g_sumsqR = 0.0; g_overlap = 0.0; g_exceed = 0.0; g_shape = 0.0; g_positive = 0.0;
        g_done = 0u; g_doneS = 0u; g_doneG = 0u;
    }
}

// ---------------- launch ----------------
extern "C" void kernel_launch(void* const* d_in, const int* in_sizes, int n_in,
                              void* d_out, int out_size) {
    const int*   idI    = (const int*)d_in[0];
    const int*   par    = (const int*)d_in[1];
    const float* omega  = (const float*)d_in[2];
    const float* child  = (const float*)d_in[3];
    const float* resv   = (const float*)d_in[4];
    const float* leaves = (const float*)d_in[5];
    const float* layerD = (const float*)d_in[6];
    (void)in_sizes; (void)n_in; (void)out_size;

    k_all<<<NTOT, 256>>>(idI, par, omega, child, resv, leaves, layerD, (float*)d_out);
}

// round 9
// speedup vs baseline: 1.5254x; 1.2090x over previous
#include <cuda_runtime.h>
#include <math.h>

#define Nn 1024
#define Cc 8192
#define ODim 128
#define EPSF 1e-15f
#define CLIPMAXF 10000.0f
#define NB 16
#define NS 8                       // s/inner/t blocks (FIRST: spin-wait, must be early)
#define NG 48                      // 3 Gram tiles x 16 K-chunks
#define NPAIR 272                  // 136 triangular 64x64 tiles x 2 j-halves
#define NTOT (NS + NG + NPAIR)     // 328

// ---------- device state (zero at load; restored each run) ----------
__device__ float    g_colR[Nn];          // atomics; re-zeroed by finalize
__device__ float    g_inner[Nn];         // overwritten
__device__ float    g_t[Nn];             // overwritten
__device__ float    g_sPart[16][ODim];   // overwritten
__device__ float    g_G[3][4096];        // atomics; re-zeroed by last G-block
__device__ double   g_normG;             // overwritten
__device__ double   g_sumsqR, g_overlap, g_exceed, g_shape, g_positive;
__device__ unsigned g_done, g_doneS, g_doneG;

__global__ void __launch_bounds__(256, 3)
k_all(const int* __restrict__ idI, const int* __restrict__ par,
      const float* __restrict__ omega, const float* __restrict__ child,
      const float* __restrict__ resv, const float* __restrict__ leaves,
      const float* __restrict__ layerDist, float* __restrict__ out)
{
    __shared__ __align__(16) char sm[33024];
    __shared__ double sAcc[8][2];
    __shared__ bool isLast;
    int tid = threadIdx.x, w = tid >> 5, lane = tid & 31;
    int b = blockIdx.x;

    if (b < NS) {
        // ========== s / inner / t blocks (early: they spin on each other) ==========
        int sb = b;
        int base = sb * 128;
        int half = tid & 1;
        {   // inner_i for 128 rows (2 threads per row)
            int row = base + (tid >> 1);
            const float4* p = (const float4*)(omega + (size_t)row * ODim + half * 64);
            float s = 0.f;
#pragma unroll
            for (int q = 0; q < 16; q++) {
                float4 v = p[q];
                s += v.x * v.x + v.y * v.y + v.z * v.z + v.w * v.w;
            }
            float o = __shfl_xor_sync(0xffffffffu, s, 1);
            if (half == 0) g_inner[row] = s + o;
        }
        {   // s partial: column sums over 64 rows
            int d = tid & 127, rh = tid >> 7;
            float sp = 0.f;
            for (int r = 0; r < 64; r++)
                sp += __ldg(omega + (size_t)(base + rh * 64 + r) * ODim + d);
            g_sPart[sb * 2 + rh][d] = sp;
        }
        __threadfence();
        __syncthreads();
        if (tid == 0) {
            atomicAdd(&g_doneS, 1u);
            volatile unsigned* ds = &g_doneS;
            while (*ds < NS) { }
        }
        __syncthreads();
        __threadfence();
        float* sS = (float*)sm;
        if (tid < ODim) {
            float s2 = 0.f;
#pragma unroll
            for (int q = 0; q < 16; q++) s2 += __ldcg(&g_sPart[q][tid]);
            sS[tid] = s2;
        }
        __syncthreads();
        {   // t_j = o_j . s
            int j = base + (tid >> 1);
            const float4* oj = (const float4*)(omega + (size_t)j * ODim + half * 64);
            const float4* s4 = (const float4*)(sS + half * 64);
            float tv = 0.f;
#pragma unroll
            for (int q = 0; q < 16; q++) {
                float4 a = oj[q], s = s4[q];
                tv += a.x * s.x + a.y * s.y + a.z * s.z + a.w * s.w;
            }
            float ot = __shfl_xor_sync(0xffffffffu, tv, 1);
            if (half == 0) g_t[j] = tv + ot;
        }
    } else if (b < NS + NG) {
        // ========== Gram: G = O^T O ==========
        float (*sO)[ODim] = (float(*)[ODim])sm;
        int gb = b - NS;
        int g = gb >> 4, kc = gb & 15;
        int P0 = (g == 2) ? 64 : 0;
        int Q0 = (g == 0) ? 0 : 64;

        const float4* og4 = (const float4*)(omega + (size_t)kc * 64 * ODim);
        for (int e = tid; e < 64 * 32; e += 256) ((float4*)sO)[e] = og4[e];
        __syncthreads();

        int pl_ = ((tid >> 4) & 15) * 4, ql_ = (tid & 15) * 4;
        float c[4][4];
#pragma unroll
        for (int m = 0; m < 4; m++)
#pragma unroll
            for (int n = 0; n < 4; n++) c[m][n] = 0.f;
#pragma unroll 8
        for (int k = 0; k < 64; k++) {
            float4 a  = *(const float4*)&sO[k][P0 + pl_];
            float4 bb = *(const float4*)&sO[k][Q0 + ql_];
            c[0][0] += a.x * bb.x; c[0][1] += a.x * bb.y; c[0][2] += a.x * bb.z; c[0][3] += a.x * bb.w;
            c[1][0] += a.y * bb.x; c[1][1] += a.y * bb.y; c[1][2] += a.y * bb.z; c[1][3] += a.y * bb.w;
            c[2][0] += a.z * bb.x; c[2][1] += a.z * bb.y; c[2][2] += a.z * bb.z; c[2][3] += a.z * bb.w;
            c[3][0] += a.w * bb.x; c[3][1] += a.w * bb.y; c[3][2] += a.w * bb.z; c[3][3] += a.w * bb.w;
        }
#pragma unroll
        for (int m = 0; m < 4; m++)
#pragma unroll
            for (int n = 0; n < 4; n++)
                atomicAdd(&g_G[g][(pl_ + m) * 64 + ql_ + n], c[m][n]);

        __threadfence();
        __shared__ bool lastG;
        if (tid == 0) lastG = (atomicAdd(&g_doneG, 1u) == NG - 1);
        __syncthreads();
        if (lastG) {
            __threadfence();
            double acc = 0.0;
            for (int e = tid; e < 3 * 4096; e += 256) {
                int gg = e >> 12, idx = e & 4095;
                float v = __ldcg(&g_G[gg][idx]);
                g_G[gg][idx] = 0.f;
                double d2 = (double)v * (double)v;
                acc += (gg == 1) ? 2.0 * d2 : d2;
            }
#pragma unroll
            for (int o = 16; o > 0; o >>= 1) acc += __shfl_xor_sync(0xffffffffu, acc, o);
            double* sR = (double*)sm;
            __syncthreads();
            if (lane == 0) sR[w] = acc;
            __syncthreads();
            if (tid == 0) {
                double tot = 0.0;
#pragma unroll
                for (int q = 0; q < 8; q++) tot += sR[q];
                g_normG = tot;
            }
        }
    } else {
        // ========== symmetric realdist: tile (bi<=bj) 64 i x 32 j ==========
        float (*sI)[48] = (float(*)[48])sm;
        int* sIdxI = (int*)(sm + 64 * 48 * 4);
        int p = b - NS - NG;
        int t = p >> 1, h = p & 1, bi = 0;
        while (t >= NB - bi) { t -= NB - bi; bi++; }
        int bj = bi + t;
        int I0 = bi * 64, J0 = bj * 64 + h * 32;

        if (tid < 64) sIdxI[tid] = __ldg(idI + I0 + tid);

        int jglob = J0 + lane;
        int idxj = __ldg(idI + jglob);
        __syncthreads();

        for (int e = tid; e < 64 * 16; e += 256) {
            int ii = e >> 4, d = e & 15;
            int ix = sIdxI[ii];
            float cl = __ldg(child + (size_t)ix * 32 + d);
            float ch = __ldg(child + (size_t)ix * 32 + 16 + d);
            sI[ii][d] = cl; sI[ii][16 + d] = ch;
            sI[ii][32 + d] = 1.0f / fmaxf(ch - cl, EPSF);
        }
        // gathers: both orders for this warp's 8 i-rows (MLP=16)
        float aij[8], aji[8];
        int ibase = I0 + w * 8;
#pragma unroll
        for (int k = 0; k < 8; k++) {
            int ix = sIdxI[w * 8 + k];
            aij[k] = __ldg(layerDist + (size_t)ix * Cc + idxj);
            aji[k] = __ldg(layerDist + (size_t)idxj * Cc + ix);
        }
        __syncthreads();

        // dim-outer / row-inner: one (l,h,v) j-triple live at a time
        float cd[8] = {0.f,0.f,0.f,0.f,0.f,0.f,0.f,0.f};
        float ov[8] = {0.f,0.f,0.f,0.f,0.f,0.f,0.f,0.f};
        const float4* pl = (const float4*)(child + (size_t)idxj * 32);
        const float4* ph = (const float4*)(child + (size_t)idxj * 32 + 16);
#pragma unroll
        for (int u = 0; u < 4; u++) {
            float4 l = pl[u], hh = ph[u];
            float4 v2;
            v2.x = 1.0f / fmaxf(hh.x - l.x, EPSF);
            v2.y = 1.0f / fmaxf(hh.y - l.y, EPSF);
            v2.z = 1.0f / fmaxf(hh.z - l.z, EPSF);
            v2.w = 1.0f / fmaxf(hh.w - l.w, EPSF);
#pragma unroll
            for (int k = 0; k < 8; k++) {
                float4 a  = *(const float4*)&sI[w * 8 + k][u * 4];
                float4 bb = *(const float4*)&sI[w * 8 + k][16 + u * 4];
                float4 vi = *(const float4*)&sI[w * 8 + k][32 + u * 4];
                cd[k] += fabsf(a.x - l.x) + fabsf(a.y - l.y)
                       + fabsf(a.z - l.z) + fabsf(a.w - l.w);
                float nx = fmaxf(fminf(bb.x, hh.x) - fmaxf(a.x, l.x), 0.f);
                float ny = fmaxf(fminf(bb.y, hh.y) - fmaxf(a.y, l.y), 0.f);
                float nz = fmaxf(fminf(bb.z, hh.z) - fmaxf(a.z, l.z), 0.f);
                float nw = fmaxf(fminf(bb.w, hh.w) - fmaxf(a.w, l.w), 0.f);
                ov[k] += nx * (vi.x + v2.x) + ny * (vi.y + v2.y)
                       + nz * (vi.z + v2.z) + nw * (vi.w + v2.w);
            }
        }

        float colsumJ = 0.f;
        double ssq = 0.0, ovd = 0.0;
#pragma unroll
        for (int k = 0; k < 8; k++) {
            int ig = ibase + k;
            float r1 = aij[k] + cd[k];
            float r2 = aji[k] + cd[k];
            float wv = 0.f;
            if (ig < jglob) {
                colsumJ += r1;
                ssq += (double)(r1 * r1 + r2 * r2);
                ovd += (double)ov[k];
                wv = r2;
            } else if (ig == jglob) {
                colsumJ += r1;
                ssq += (double)(r1 * r1);
            }
#pragma unroll
            for (int o = 16; o > 0; o >>= 1) wv += __shfl_xor_sync(0xffffffffu, wv, o);
            if (lane == 0 && wv != 0.f) atomicAdd(&g_colR[ig], wv);
        }
        atomicAdd(&g_colR[jglob], colsumJ);

        // block-level fp64 reduce: 1 atomic per scalar per block
#pragma unroll
        for (int o = 16; o > 0; o >>= 1) {
            ssq += __shfl_xor_sync(0xffffffffu, ssq, o);
            ovd += __shfl_xor_sync(0xffffffffu, ovd, o);
        }
        if (lane == 0) { sAcc[w][0] = ssq; sAcc[w][1] = ovd; }
        __syncthreads();
        if (tid == 0) {
            double t0 = 0.0, t1 = 0.0;
#pragma unroll
            for (int q = 0; q < 8; q++) { t0 += sAcc[q][0]; t1 += sAcc[q][1]; }
            atomicAdd(&g_sumsqR, t0);
            atomicAdd(&g_overlap, t1);
        }

        // ---- per-node prep: first 32 pair blocks (bi==0), warp 0, lane's j ----
        if (p < 32 && w == 0) {
            int pp = __ldg(par + jglob);
            float leaf = __ldg(leaves + idxj);
            const float HPI = (float)(3.14159265358979323846 * 0.5);
            const float CAP = (float)(3.14159265358979323846 * 0.49999);
            const float4* prl = (const float4*)(resv + (size_t)pp * 32);
            const float4* prh = (const float4*)(resv + (size_t)pp * 32 + 16);
            float exceed = 0.f, shape = 0.f, pos = 0.f;
#pragma unroll
            for (int u = 0; u < 4; u++) {
                float4 cl = pl[u], ch = ph[u];
                float4 rl = prl[u], rh = prh[u];
                float cc[4] = {cl.x, cl.y, cl.z, cl.w};
                float ee[4] = {ch.x, ch.y, ch.z, ch.w};
                float aa[4] = {rl.x, rl.y, rl.z, rl.w};
                float zz[4] = {rh.x, rh.y, rh.z, rh.w};
#pragma unroll
                for (int d = 0; d < 4; d++) {
                    float diff = ee[d] - cc[d];
                    exceed += fmaxf((aa[d] + 1.0f) - cc[d], 0.f)
                            + fmaxf(ee[d] - (zz[d] + 1.0f), 0.f);
                    float numer = fmaxf(diff / (zz[d] - aa[d]), EPSF);
                    float sdiv  = fminf(numer / leaf, CAP);
                    shape += fminf(fabsf(tanf((sdiv - 1.0f) * HPI)), CLIPMAXF);
                    pos += fmaxf(expf(-diff), EPSF);
                }
            }
            double e = exceed, sh = shape, po = pos;
#pragma unroll
            for (int o = 16; o > 0; o >>= 1) {
                e  += __shfl_xor_sync(0xffffffffu, e,  o);
                sh += __shfl_xor_sync(0xffffffffu, sh, o);
                po += __shfl_xor_sync(0xffffffffu, po, o);
            }
            if (lane == 0) {
                atomicAdd(&g_exceed, e);
                atomicAdd(&g_shape, sh);
                atomicAdd(&g_positive, po);
            }
        }
    }

    // ================= last-block finalize + state restore =================
    __threadfence();
    if (tid == 0) isLast = (atomicAdd(&g_done, 1u) == NTOT - 1);
    __syncthreads();
    if (!isLast) return;
    __threadfence();

    double S1 = 0, S2 = 0, T1 = 0, CR = 0, CRI = 0, CRT = 0, s2a = 0;
#pragma unroll
    for (int q = 0; q < 4; q++) {
        int j = tid + q * 256;
        double inn = (double)__ldcg(&g_inner[j]);
        double tj  = (double)__ldcg(&g_t[j]);
        double cr  = (double)__ldcg(&g_colR[j]);
        g_colR[j] = 0.f;
        S1 += inn; S2 += inn * inn; T1 += inn * tj;
        CR += cr; CRI += cr * inn; CRT += cr * tj; s2a += cr * cr;
    }
#pragma unroll
    for (int o = 16; o > 0; o >>= 1) {
        S1 += __shfl_xor_sync(0xffffffffu, S1, o);
        S2 += __shfl_xor_sync(0xffffffffu, S2, o);
        T1 += __shfl_xor_sync(0xffffffffu, T1, o);
        CR += __shfl_xor_sync(0xffffffffu, CR, o);
        CRI += __shfl_xor_sync(0xffffffffu, CRI, o);
        CRT += __shfl_xor_sync(0xffffffffu, CRT, o);
        s2a += __shfl_xor_sync(0xffffffffu, s2a, o);
    }
    double* sR = (double*)sm;
    __syncthreads();
    if (lane == 0) {
        sR[w * 7 + 0] = S1; sR[w * 7 + 1] = S2; sR[w * 7 + 2] = T1;
        sR[w * 7 + 3] = CR; sR[w * 7 + 4] = CRI; sR[w * 7 + 5] = CRT;
        sR[w * 7 + 6] = s2a;
    }
    __syncthreads();
    if (tid == 0) {
        double a0 = 0, a1 = 0, a2 = 0, a3 = 0, a4 = 0, a5 = 0, a6 = 0;
#pragma unroll
        for (int q = 0; q < 8; q++) {
            a0 += sR[q * 7 + 0]; a1 += sR[q * 7 + 1]; a2 += sR[q * 7 + 2];
            a3 += sR[q * 7 + 3]; a4 += sR[q * 7 + 4]; a5 += sR[q * 7 + 5];
            a6 += sR[q * 7 + 6];
        }
        double sumsqA = 2.0 * Nn * a1 + 2.0 * a0 * a0 - 8.0 * a2 + 4.0 * __ldcg(&g_normG);
        double s1 = a0 * a3 + (double)Nn * a4 - 2.0 * a5 + (double)EPSF * a3;
        double sumsqR = __ldcg(&g_sumsqR);
        double nR = fmax(sqrt(sumsqR), 1e-15);
        double nA = fmax(sqrt(fmax(sumsqA, 0.0)), 1e-15);
        double val = sumsqA / (nA * nA) - 2.0 * (s1 / nR) / nA + (double)Nn * (a6 / (nR * nR));
        double lossDist = sqrt(fmax(val, 0.0));
        out[0] = (float)(lossDist + __ldcg(&g_shape) + __ldcg(&g_exceed)
                         + __ldcg(&g_overlap) + __ldcg(&g_positive));
        g_sumsqR = 0.0; g_overlap = 0.0; g_exceed = 0.0; g_shape = 0.0; g_positive = 0.0;
        g_done = 0u; g_doneS = 0u; g_doneG = 0u;
    }
}

// ---------------- launch ----------------
extern "C" void kernel_launch(void* const* d_in, const int* in_sizes, int n_in,
                              void* d_out, int out_size) {
    const int*   idI    = (const int*)d_in[0];
    const int*   par    = (const int*)d_in[1];
    const float* omega  = (const float*)d_in[2];
    const float* child  = (const float*)d_in[3];
    const float* resv   = (const float*)d_in[4];
    const float* leaves = (const float*)d_in[5];
    const float* layerD = (const float*)d_in[6];
    (void)in_sizes; (void)n_in; (void)out_size;

    k_all<<<NTOT, 256>>>(idI, par, omega, child, resv, leaves, layerD, (float*)d_out);
}